// round 1
// baseline (speedup 1.0000x reference)
#include <cuda_runtime.h>
#include <cuda_bf16.h>
#include <math.h>
#include <stdint.h>

// Problem constants
#define A_N 110484          // number of anchors
#define C_N 90              // classes
#define KC  512             // K_CAND
#define HB  8192            // histogram buckets (float bits >> 17; scores in (0,1) -> bucket < 8128)
#define SHIFT 17
#define IMGF 768.0f
#define THRESH 0.05f
#define IOU_T 0.5f
#define MAXDET 100
#define TOT (C_N * KC)      // 46080

// ---------------- scratch (device globals; no runtime allocation) ----------------
__device__ float  g_scoresT[(size_t)C_N * A_N];   // (90, A) sigmoid scores, ~39.8MB
__device__ float4 g_boxes[A_N];                   // decoded boxes
__device__ int    g_hist[C_N * HB];               // per-class histograms
__device__ int    g_cut[C_N];                     // per-class cutoff bucket
__device__ float  g_vals[TOT];                    // per-class top-512 scores (sorted desc)
__device__ float4 g_cboxes[TOT];                  // candidate boxes
__device__ float  g_kept[TOT];                    // kept score or -1
__device__ int    g_hist2[HB];
__device__ int    g_cut2;

// ---------------- K1: decode + clip boxes ----------------
__global__ void k_decode(const float* __restrict__ reg, const float* __restrict__ anc) {
    int i = blockIdx.x * blockDim.x + threadIdx.x;
    if (i >= A_N) return;
    float4 a = ((const float4*)anc)[i];
    float4 d = ((const float4*)reg)[i];
    float wa = a.z - a.x, ha = a.w - a.y;
    float cxa = a.x + 0.5f * wa, cya = a.y + 0.5f * ha;
    float cx = cxa + d.x * wa;
    float cy = cya + d.y * ha;
    float w = expf(d.z) * wa;
    float h = expf(d.w) * ha;
    float x1 = fminf(fmaxf(cx - 0.5f * w, 0.0f), IMGF);
    float y1 = fminf(fmaxf(cy - 0.5f * h, 0.0f), IMGF);
    float x2 = fminf(fmaxf(cx + 0.5f * w, 0.0f), IMGF);
    float y2 = fminf(fmaxf(cy + 0.5f * h, 0.0f), IMGF);
    g_boxes[i] = make_float4(x1, y1, x2, y2);
}

// ---------------- K2: transpose + sigmoid ----------------
__global__ void k_transpose(const float* __restrict__ cls) {
    __shared__ float tile[32][33];
    int a = blockIdx.x * 32 + threadIdx.y;
    int c = blockIdx.y * 32 + threadIdx.x;
    if (a < A_N && c < C_N)
        tile[threadIdx.y][threadIdx.x] = cls[(size_t)a * C_N + c];
    __syncthreads();
    int c2 = blockIdx.y * 32 + threadIdx.y;
    int a2 = blockIdx.x * 32 + threadIdx.x;
    if (c2 < C_N && a2 < A_N) {
        float x = tile[threadIdx.x][threadIdx.y];
        g_scoresT[(size_t)c2 * A_N + a2] = 1.0f / (1.0f + expf(-x));
    }
}

// ---------------- K3: per-class histogram over float-bit buckets ----------------
__global__ void k_hist(void) {
    __shared__ int sh[HB];
    int c = blockIdx.x;
    for (int b = threadIdx.x; b < HB; b += blockDim.x) sh[b] = 0;
    __syncthreads();
    const float* sc = &g_scoresT[(size_t)c * A_N];
    for (int a = threadIdx.x; a < A_N; a += blockDim.x) {
        unsigned u = __float_as_uint(sc[a]);
        atomicAdd(&sh[u >> SHIFT], 1);
    }
    __syncthreads();
    for (int b = threadIdx.x; b < HB; b += blockDim.x) g_hist[c * HB + b] = sh[b];
}

// ---------------- generic cutoff finder: max bucket b with suffix_count(b) >= need ----
__device__ int find_cut(const int* hist, int need) {
    __shared__ int partial[256];
    __shared__ int result;
    int t = threadIdx.x;
    // chunk t covers buckets [HB-(t+1)*32, HB-t*32) (descending chunks)
    int s = 0;
    int lo = HB - (t + 1) * 32;
    for (int b = lo; b < lo + 32; b++) s += hist[b];
    partial[t] = s;
    __syncthreads();
    if (t == 0) {
        int cum = 0, kmin = 0;
        for (int tc = 0; tc < 256; tc++) {
            if (cum + partial[tc] >= need) {
                int hi = HB - tc * 32 - 1;
                for (int b = hi; b >= hi - 31; b--) {
                    cum += hist[b];
                    if (cum >= need) { kmin = b; break; }
                }
                result = kmin;
                cum = -1; // mark found
                break;
            }
            cum += partial[tc];
        }
        if (cum >= 0) result = 0; // not enough elements: take everything
    }
    __syncthreads();
    return result;
}

__global__ void k_cut(void) {
    int c = blockIdx.x;
    int km = find_cut(&g_hist[c * HB], KC);
    if (threadIdx.x == 0) g_cut[c] = km;
}

// ---------------- bitonic sort helper (descending, u64 keys in shared) ------------
template <int N>
__device__ void bitonic_desc(unsigned long long* keys) {
    for (int k = 2; k <= N; k <<= 1) {
        for (int j = k >> 1; j > 0; j >>= 1) {
            for (int i = threadIdx.x; i < N; i += blockDim.x) {
                int ix = i ^ j;
                if (ix > i) {
                    unsigned long long x = keys[i], y = keys[ix];
                    bool descSeg = ((i & k) == 0);
                    if (descSeg ? (x < y) : (x > y)) { keys[i] = y; keys[ix] = x; }
                }
            }
            __syncthreads();
        }
    }
}

// ---------------- K5: gather candidates >= cutoff, sort, emit top-512 -------------
#define GCAP 4096
__global__ void k_gather(void) {
    __shared__ unsigned long long keys[GCAP];
    __shared__ int cnt;
    int c = blockIdx.x;
    int kmin = g_cut[c];
    for (int i = threadIdx.x; i < GCAP; i += blockDim.x) keys[i] = 0ULL;
    if (threadIdx.x == 0) cnt = 0;
    __syncthreads();
    const float* sc = &g_scoresT[(size_t)c * A_N];
    for (int a = threadIdx.x; a < A_N; a += blockDim.x) {
        unsigned u = __float_as_uint(sc[a]);
        if ((int)(u >> SHIFT) >= kmin) {
            int p = atomicAdd(&cnt, 1);
            if (p < GCAP)
                keys[p] = ((unsigned long long)u << 32) | (unsigned)(0xFFFFFFFFu - (unsigned)a);
        }
    }
    __syncthreads();
    bitonic_desc<GCAP>(keys);
    int t = threadIdx.x;
    if (t < KC) {
        unsigned long long key = keys[t];
        unsigned ub = (unsigned)(key >> 32);
        unsigned idx = 0xFFFFFFFFu - (unsigned)(key & 0xFFFFFFFFu);
        g_vals[c * KC + t] = __uint_as_float(ub);
        g_cboxes[c * KC + t] = g_boxes[idx];
    }
}

// ---------------- K6: per-class greedy NMS (exact scan semantics) -----------------
__global__ void k_nms(void) {
    __shared__ float4 sbox;
    __shared__ int skeep;
    int c = blockIdx.x;
    int t = threadIdx.x;
    float val = g_vals[c * KC + t];
    float4 b = g_cboxes[c * KC + t];
    float area = (b.z - b.x) * (b.w - b.y);
    bool valid = val > THRESH;
    bool suppressed = false;
    bool keep = false;
    for (int i = 0; i < KC; i++) {
        if (t == i) {
            keep = valid && !suppressed;
            skeep = keep ? 1 : 0;
            sbox = b;
        }
        __syncthreads();
        if (skeep) {
            float xx1 = fmaxf(sbox.x, b.x), yy1 = fmaxf(sbox.y, b.y);
            float xx2 = fminf(sbox.z, b.z), yy2 = fminf(sbox.w, b.w);
            float inter = fmaxf(xx2 - xx1, 0.0f) * fmaxf(yy2 - yy1, 0.0f);
            float sarea = (sbox.z - sbox.x) * (sbox.w - sbox.y);
            float iou = inter / (sarea + area - inter + 1e-8f);
            if (iou > IOU_T) suppressed = true;
        }
        __syncthreads();
    }
    g_kept[c * KC + t] = keep ? val : -1.0f;
}

// ---------------- K7: histogram of kept (positive) scores -------------------------
__global__ void k_hist2(void) {
    __shared__ int sh[HB];
    for (int b = threadIdx.x; b < HB; b += blockDim.x) sh[b] = 0;
    __syncthreads();
    for (int i = threadIdx.x; i < TOT; i += blockDim.x) {
        float v = g_kept[i];
        if (v > 0.0f) {
            unsigned u = __float_as_uint(v);
            atomicAdd(&sh[u >> SHIFT], 1);
        }
    }
    __syncthreads();
    for (int b = threadIdx.x; b < HB; b += blockDim.x) g_hist2[b] = sh[b];
}

__global__ void k_cut2(void) {
    int km = find_cut(g_hist2, MAXDET);
    if (threadIdx.x == 0) g_cut2 = km;
}

// ---------------- K9: final top-100 + output assembly -----------------------------
#define FCAP 2048
__global__ void k_final(float* __restrict__ out) {
    __shared__ unsigned long long keys[FCAP];
    __shared__ int cnt;
    for (int i = threadIdx.x; i < FCAP; i += blockDim.x) keys[i] = 0ULL;
    if (threadIdx.x == 0) cnt = 0;
    __syncthreads();
    int kmin = g_cut2;
    for (int i = threadIdx.x; i < TOT; i += blockDim.x) {
        float v = g_kept[i];
        if (v > 0.0f) {
            unsigned u = __float_as_uint(v);
            if ((int)(u >> SHIFT) >= kmin) {
                int p = atomicAdd(&cnt, 1);
                if (p < FCAP)
                    keys[p] = ((unsigned long long)u << 32) | (unsigned)(0xFFFFFFFFu - (unsigned)i);
            }
        }
    }
    __syncthreads();
    bitonic_desc<FCAP>(keys);
    int t = threadIdx.x;
    if (t < MAXDET) {
        unsigned long long key = keys[t];
        float* row = out + t * 7;
        if (key == 0ULL) {
            for (int q = 0; q < 7; q++) row[q] = 0.0f;
        } else {
            unsigned ub = (unsigned)(key >> 32);
            unsigned flat = 0xFFFFFFFFu - (unsigned)(key & 0xFFFFFFFFu);
            float v = __uint_as_float(ub);
            float4 bb = g_cboxes[flat];
            row[0] = 0.0f;
            row[1] = bb.x; row[2] = bb.y; row[3] = bb.z; row[4] = bb.w;
            row[5] = v;
            row[6] = (float)(flat / KC);
        }
    }
}

// ---------------- launch ----------------------------------------------------------
extern "C" void kernel_launch(void* const* d_in, const int* in_sizes, int n_in,
                              void* d_out, int out_size) {
    const float* reg = (const float*)d_in[1];
    const float* cls = (const float*)d_in[2];
    const float* anc = (const float*)d_in[3];
    float* out = (float*)d_out;

    k_decode<<<(A_N + 255) / 256, 256>>>(reg, anc);
    k_transpose<<<dim3((A_N + 31) / 32, (C_N + 31) / 32), dim3(32, 32)>>>(cls);
    k_hist<<<C_N, 256>>>();
    k_cut<<<C_N, 256>>>();
    k_gather<<<C_N, 512>>>();
    k_nms<<<C_N, 512>>>();
    k_hist2<<<1, 1024>>>();
    k_cut2<<<1, 256>>>();
    k_final<<<1, 1024>>>(out);
}

// round 2
// speedup vs baseline: 1.0655x; 1.0655x over previous
#include <cuda_runtime.h>
#include <cuda_bf16.h>
#include <math.h>
#include <stdint.h>

#define A_N 110484          // anchors
#define C_N 90              // classes
#define KC  512             // K_CAND
#define HB  8192            // histogram buckets
#define SH_CLS 19           // bucket shift for order-transformed logit bits
#define SH_FIN 17           // bucket shift for sigmoid score bits (scores in (0,1))
#define IMGF 768.0f
#define THRESH 0.05f
#define IOU_T 0.5f
#define MAXDET 100
#define TOT (C_N * KC)      // 46080
#define GCAP 4096
#define FCAP 2048

// ---------------- scratch (device globals) ----------------
__device__ float  g_xT[(size_t)C_N * A_N];   // (90, A) raw logits transposed
__device__ float4 g_boxes[A_N];              // decoded boxes
__device__ float  g_kept[TOT];               // kept score or -1
__device__ float4 g_cboxes[TOT];             // candidate boxes (per class, sorted desc)

// order-preserving transform: float total order -> unsigned order
__device__ __forceinline__ unsigned fkey(unsigned u) {
    return u ^ ((u & 0x80000000u) ? 0xFFFFFFFFu : 0x80000000u);
}
__device__ __forceinline__ unsigned fkey_inv(unsigned k) {
    return (k & 0x80000000u) ? (k ^ 0x80000000u) : ~k;
}

// ---------------- K1: decode + clip boxes ----------------
__global__ void k_decode(const float* __restrict__ reg, const float* __restrict__ anc) {
    int i = blockIdx.x * blockDim.x + threadIdx.x;
    if (i >= A_N) return;
    float4 a = ((const float4*)anc)[i];
    float4 d = ((const float4*)reg)[i];
    float wa = a.z - a.x, ha = a.w - a.y;
    float cxa = a.x + 0.5f * wa, cya = a.y + 0.5f * ha;
    float cx = cxa + d.x * wa;
    float cy = cya + d.y * ha;
    float w = expf(d.z) * wa;
    float h = expf(d.w) * ha;
    float x1 = fminf(fmaxf(cx - 0.5f * w, 0.0f), IMGF);
    float y1 = fminf(fmaxf(cy - 0.5f * h, 0.0f), IMGF);
    float x2 = fminf(fmaxf(cx + 0.5f * w, 0.0f), IMGF);
    float y2 = fminf(fmaxf(cy + 0.5f * h, 0.0f), IMGF);
    g_boxes[i] = make_float4(x1, y1, x2, y2);
}

// ---------------- K2: transpose (raw logits, no sigmoid) ----------------
__global__ void k_transpose(const float* __restrict__ cls) {
    __shared__ float tile[32][33];
    int a = blockIdx.x * 32 + threadIdx.y;
    int c = blockIdx.y * 32 + threadIdx.x;
    if (a < A_N && c < C_N)
        tile[threadIdx.y][threadIdx.x] = cls[(size_t)a * C_N + c];
    __syncthreads();
    int c2 = blockIdx.y * 32 + threadIdx.y;
    int a2 = blockIdx.x * 32 + threadIdx.x;
    if (c2 < C_N && a2 < A_N)
        g_xT[(size_t)c2 * A_N + a2] = tile[threadIdx.x][threadIdx.y];
}

// ---------------- K3: fused per-class hist + cutoff + gather + sort + NMS --------
__global__ void __launch_bounds__(512) k_class(void) {
    __shared__ union {
        int hist[HB];                      // 32 KB
        unsigned long long keys[GCAP];     // 32 KB (reused after cutoff)
    } U;
    __shared__ float4 sbox[KC];            // 8 KB
    __shared__ float  sval[KC];            // 2 KB
    __shared__ int    partial[512];        // 2 KB
    __shared__ int    s_kmin, s_cnt, s_next;
    __shared__ unsigned sball[16];

    int c = blockIdx.x, t = threadIdx.x;
    const float* row = &g_xT[(size_t)c * A_N];

    // --- histogram over order-transformed logit bits ---
    for (int b = t; b < HB; b += 512) U.hist[b] = 0;
    if (t == 0) s_cnt = 0;
    __syncthreads();
    const float4* row4 = (const float4*)row;
    const int N4 = A_N / 4;
    for (int a = t; a < N4; a += 512) {
        float4 v = row4[a];
        atomicAdd(&U.hist[fkey(__float_as_uint(v.x)) >> SH_CLS], 1);
        atomicAdd(&U.hist[fkey(__float_as_uint(v.y)) >> SH_CLS], 1);
        atomicAdd(&U.hist[fkey(__float_as_uint(v.z)) >> SH_CLS], 1);
        atomicAdd(&U.hist[fkey(__float_as_uint(v.w)) >> SH_CLS], 1);
    }
    __syncthreads();

    // --- parallel cutoff: descending chunk sums + inclusive scan ---
    const int CH = HB / 512;               // 16 buckets per thread
    int lo = HB - (t + 1) * CH;
    int s = 0;
    #pragma unroll
    for (int b = 0; b < CH; b++) s += U.hist[lo + b];
    partial[t] = s;
    __syncthreads();
    for (int off = 1; off < 512; off <<= 1) {
        int v = (t >= off) ? partial[t - off] : 0;
        __syncthreads();
        partial[t] += v;
        __syncthreads();
    }
    int incl = partial[t];
    int prev = t ? partial[t - 1] : 0;
    if (prev < KC && incl >= KC) {         // exactly one thread (total >= KC always)
        int cum = prev;
        for (int b = HB - 1 - t * CH; b >= lo; b--) {
            cum += U.hist[b];
            if (cum >= KC) { s_kmin = b; break; }
        }
    }
    __syncthreads();
    int kmin = s_kmin;

    // --- reuse U as sort keys: zero, then gather candidates >= cutoff bucket ---
    for (int i = t; i < GCAP; i += 512) U.keys[i] = 0ULL;
    __syncthreads();
    for (int a = t; a < N4; a += 512) {
        float4 v = row4[a];
        #pragma unroll
        for (int q = 0; q < 4; q++) {
            float vv = (q == 0) ? v.x : (q == 1) ? v.y : (q == 2) ? v.z : v.w;
            unsigned k = fkey(__float_as_uint(vv));
            if ((int)(k >> SH_CLS) >= kmin) {
                int p = atomicAdd(&s_cnt, 1);
                if (p < GCAP) {
                    unsigned aidx = (unsigned)(a * 4 + q);
                    U.keys[p] = ((unsigned long long)k << 32) | (0xFFFFFFFFu - aidx);
                }
            }
        }
    }
    __syncthreads();

    // --- bitonic sort (descending) of next_pow2(cnt) elements ---
    int cnt = s_cnt; if (cnt > GCAP) cnt = GCAP;
    int N = 512; while (N < cnt) N <<= 1; if (N > GCAP) N = GCAP;
    for (int k2 = 2; k2 <= N; k2 <<= 1) {
        for (int j = k2 >> 1; j > 0; j >>= 1) {
            for (int i = t; i < N; i += 512) {
                int ix = i ^ j;
                if (ix > i) {
                    unsigned long long x = U.keys[i], y = U.keys[ix];
                    bool desc = ((i & k2) == 0);
                    if (desc ? (x < y) : (x > y)) { U.keys[i] = y; U.keys[ix] = x; }
                }
            }
            __syncthreads();
        }
    }

    // --- extract top-512: sigmoid only on survivors; fetch boxes ---
    {
        unsigned long long key = U.keys[t];
        unsigned kb  = (unsigned)(key >> 32);
        unsigned idx = 0xFFFFFFFFu - (unsigned)(key & 0xFFFFFFFFu);
        float x = __uint_as_float(fkey_inv(kb));
        sval[t] = 1.0f / (1.0f + expf(-x));
        sbox[t] = g_boxes[idx];
    }
    __syncthreads();

    // --- greedy NMS, frontier form (iterations = #kept, not 512) ---
    float4 b = sbox[t];
    float val = sval[t];
    float area = (b.z - b.x) * (b.w - b.y);
    int nvalid = __syncthreads_count(val > THRESH);  // valid is a prefix (sorted desc)
    bool suppressed = false, keep = false;
    int warpId = t >> 5, lane = t & 31;
    int cur = (nvalid > 0) ? 0 : KC;
    while (cur < nvalid) {
        if (t == cur) keep = true;
        float4 cb = sbox[cur];
        if (t > cur && t < nvalid && !suppressed) {
            float xx1 = fmaxf(cb.x, b.x), yy1 = fmaxf(cb.y, b.y);
            float xx2 = fminf(cb.z, b.z), yy2 = fminf(cb.w, b.w);
            float inter = fmaxf(xx2 - xx1, 0.0f) * fmaxf(yy2 - yy1, 0.0f);
            float ca = (cb.z - cb.x) * (cb.w - cb.y);
            float iou = inter / (ca + area - inter + 1e-8f);
            if (iou > IOU_T) suppressed = true;
        }
        bool pred = (t > cur) && (t < nvalid) && !suppressed;
        unsigned m = __ballot_sync(0xFFFFFFFFu, pred);
        if (lane == 0) sball[warpId] = m;
        __syncthreads();
        if (t == 0) {
            int nx = KC;
            #pragma unroll
            for (int w = 0; w < 16; w++) {
                unsigned mm = sball[w];
                if (mm) { nx = w * 32 + __ffs(mm) - 1; break; }
            }
            s_next = nx;
        }
        __syncthreads();
        cur = s_next;
    }

    g_kept[c * KC + t]   = keep ? val : -1.0f;
    g_cboxes[c * KC + t] = b;
}

// ---------------- K4: fused final top-100 + output ----------------
__global__ void __launch_bounds__(1024) k_final(float* __restrict__ out) {
    __shared__ union {
        int hist[HB];                      // 32 KB
        unsigned long long keys[FCAP];     // 16 KB
    } U;
    __shared__ int partial[1024];
    __shared__ int s_kmin, s_cnt;
    int t = threadIdx.x;

    for (int b = t; b < HB; b += 1024) U.hist[b] = 0;
    if (t == 0) { s_kmin = 0; s_cnt = 0; }
    __syncthreads();
    for (int i = t; i < TOT; i += 1024) {
        float v = g_kept[i];
        if (v > 0.0f) atomicAdd(&U.hist[__float_as_uint(v) >> SH_FIN], 1);
    }
    __syncthreads();

    const int CH = HB / 1024;
    int lo = HB - (t + 1) * CH;
    int s = 0;
    #pragma unroll
    for (int b = 0; b < CH; b++) s += U.hist[lo + b];
    partial[t] = s;
    __syncthreads();
    for (int off = 1; off < 1024; off <<= 1) {
        int v = (t >= off) ? partial[t - off] : 0;
        __syncthreads();
        partial[t] += v;
        __syncthreads();
    }
    int incl = partial[t];
    int prev = t ? partial[t - 1] : 0;
    if (prev < MAXDET && incl >= MAXDET) {
        int cum = prev;
        for (int b = HB - 1 - t * CH; b >= lo; b--) {
            cum += U.hist[b];
            if (cum >= MAXDET) { s_kmin = b; break; }
        }
    }
    __syncthreads();
    int kmin = s_kmin;    // stays 0 if fewer than 100 positives: take all

    for (int i = t; i < FCAP; i += 1024) U.keys[i] = 0ULL;
    __syncthreads();
    for (int i = t; i < TOT; i += 1024) {
        float v = g_kept[i];
        if (v > 0.0f) {
            unsigned u = __float_as_uint(v);
            if ((int)(u >> SH_FIN) >= kmin) {
                int p = atomicAdd(&s_cnt, 1);
                if (p < FCAP)
                    U.keys[p] = ((unsigned long long)u << 32) | (0xFFFFFFFFu - (unsigned)i);
            }
        }
    }
    __syncthreads();

    int cnt = s_cnt; if (cnt > FCAP) cnt = FCAP;
    int N = 128; while (N < cnt) N <<= 1; if (N > FCAP) N = FCAP;
    for (int k2 = 2; k2 <= N; k2 <<= 1) {
        for (int j = k2 >> 1; j > 0; j >>= 1) {
            for (int i = t; i < N; i += 1024) {
                int ix = i ^ j;
                if (ix > i) {
                    unsigned long long x = U.keys[i], y = U.keys[ix];
                    bool d = ((i & k2) == 0);
                    if (d ? (x < y) : (x > y)) { U.keys[i] = y; U.keys[ix] = x; }
                }
            }
            __syncthreads();
        }
    }

    if (t < MAXDET) {
        unsigned long long key = U.keys[t];
        float* rowp = out + t * 7;
        if (key == 0ULL) {
            #pragma unroll
            for (int q = 0; q < 7; q++) rowp[q] = 0.0f;
        } else {
            unsigned ub = (unsigned)(key >> 32);
            unsigned flat = 0xFFFFFFFFu - (unsigned)(key & 0xFFFFFFFFu);
            float v = __uint_as_float(ub);
            float4 bb = g_cboxes[flat];
            rowp[0] = 0.0f;
            rowp[1] = bb.x; rowp[2] = bb.y; rowp[3] = bb.z; rowp[4] = bb.w;
            rowp[5] = v;
            rowp[6] = (float)(flat / KC);
        }
    }
}

// ---------------- launch ----------------
extern "C" void kernel_launch(void* const* d_in, const int* in_sizes, int n_in,
                              void* d_out, int out_size) {
    const float* reg = (const float*)d_in[1];
    const float* cls = (const float*)d_in[2];
    const float* anc = (const float*)d_in[3];
    float* out = (float*)d_out;

    k_decode<<<(A_N + 255) / 256, 256>>>(reg, anc);
    k_transpose<<<dim3((A_N + 31) / 32, (C_N + 31) / 32), dim3(32, 32)>>>(cls);
    k_class<<<C_N, 512>>>();
    k_final<<<1, 1024>>>(out);
}

// round 5
// speedup vs baseline: 1.3573x; 1.2738x over previous
#include <cuda_runtime.h>
#include <cuda_bf16.h>
#include <math.h>
#include <stdint.h>

#define A_N 110484          // anchors
#define C_N 90              // classes
#define KC  512             // K_CAND
#define IMGF 768.0f
#define THRESH 0.05f
#define IOU_T 0.5f
#define MAXDET 100
#define TOT (C_N * KC)      // 46080
#define GCAP 4096
#define FCAP 2048
#define STOP_CLASS 1024     // stop radix refine when candidate set <= this
#define STOP_FIN   512

// ---------------- scratch (device globals) ----------------
__device__ float  g_xT[(size_t)C_N * A_N];   // (90, A) raw logits transposed
__device__ float4 g_boxes[A_N];              // decoded boxes
__device__ float  g_kept[TOT];               // kept score or -1
__device__ float4 g_cboxes[TOT];             // candidate boxes (per class, sorted desc)

// order-preserving transform: float total order -> unsigned order
__device__ __forceinline__ unsigned fkey(unsigned u) {
    return u ^ ((u & 0x80000000u) ? 0xFFFFFFFFu : 0x80000000u);
}
__device__ __forceinline__ unsigned fkey_inv(unsigned k) {
    return (k & 0x80000000u) ? (k ^ 0x80000000u) : ~k;
}

// ---------------- K1: decode + clip boxes ----------------
__global__ void k_decode(const float* __restrict__ reg, const float* __restrict__ anc) {
    int i = blockIdx.x * blockDim.x + threadIdx.x;
    if (i >= A_N) return;
    float4 a = ((const float4*)anc)[i];
    float4 d = ((const float4*)reg)[i];
    float wa = a.z - a.x, ha = a.w - a.y;
    float cxa = a.x + 0.5f * wa, cya = a.y + 0.5f * ha;
    float cx = cxa + d.x * wa;
    float cy = cya + d.y * ha;
    float w = expf(d.z) * wa;
    float h = expf(d.w) * ha;
    float x1 = fminf(fmaxf(cx - 0.5f * w, 0.0f), IMGF);
    float y1 = fminf(fmaxf(cy - 0.5f * h, 0.0f), IMGF);
    float x2 = fminf(fmaxf(cx + 0.5f * w, 0.0f), IMGF);
    float y2 = fminf(fmaxf(cy + 0.5f * h, 0.0f), IMGF);
    g_boxes[i] = make_float4(x1, y1, x2, y2);
}

// ---------------- K2: transpose (raw logits) ----------------
__global__ void k_transpose(const float* __restrict__ cls) {
    __shared__ float tile[32][33];
    int a = blockIdx.x * 32 + threadIdx.y;
    int c = blockIdx.y * 32 + threadIdx.x;
    if (a < A_N && c < C_N)
        tile[threadIdx.y][threadIdx.x] = cls[(size_t)a * C_N + c];
    __syncthreads();
    int c2 = blockIdx.y * 32 + threadIdx.y;
    int a2 = blockIdx.x * 32 + threadIdx.x;
    if (c2 < C_N && a2 < A_N)
        g_xT[(size_t)c2 * A_N + a2] = tile[threadIdx.x][threadIdx.y];
}

// ----- shared radix-select machinery: count 16 sub-buckets with packed regs -----
// Counts per thread per level must stay < 256 (A_N/512 = 216, TOT/1024 = 45: ok).

// ---------------- K3: fused per-class select + sort + NMS --------
__global__ void __launch_bounds__(512) k_class(void) {
    __shared__ union {
        unsigned long long keys[GCAP];     // 32 KB
        unsigned bits[KC][16];             // 32 KB IoU suppression matrix
    } U;
    __shared__ float4 sbox[KC];            // 8 KB
    __shared__ float  sval[KC];            // 2 KB
    __shared__ float  sarea[KC];           // 2 KB
    __shared__ int    s_tot[16];
    __shared__ int    s_cnt;
    __shared__ unsigned s_keep[16];

    const int c = blockIdx.x, t = threadIdx.x;
    const int lane = t & 31;
    const float4* row4 = (const float4*)&g_xT[(size_t)c * A_N];
    const int N4 = A_N / 4;

    // ---- multi-level radix select: find prefix such that count(key >= prefix) in (512, STOP] ----
    unsigned pref = 0, maskhi = 0;
    int pbits = 0, above = 0, active = 0;

    while (true) {
        if (t < 16) s_tot[t] = 0;
        __syncthreads();
        const int sh = 28 - pbits;
        unsigned long long accLo = 0, accHi = 0;
        for (int a = t; a < N4; a += 512) {
            float4 v = row4[a];
            float vv[4] = {v.x, v.y, v.z, v.w};
            #pragma unroll
            for (int q = 0; q < 4; q++) {
                unsigned key = fkey(__float_as_uint(vv[q]));
                unsigned m = ((key & maskhi) == pref) ? 1u : 0u;
                unsigned b = (key >> sh) & 15u;
                unsigned long long inc = (unsigned long long)m << ((b & 7u) * 8u);
                if (b < 8u) accLo += inc; else accHi += inc;
            }
        }
        // unpack + warp reduce + shared accumulate
        int cnt[16];
        #pragma unroll
        for (int b = 0; b < 8; b++)  cnt[b]     = (int)((accLo >> (8 * b)) & 0xFF);
        #pragma unroll
        for (int b = 0; b < 8; b++)  cnt[b + 8] = (int)((accHi >> (8 * b)) & 0xFF);
        #pragma unroll
        for (int off = 16; off > 0; off >>= 1) {
            #pragma unroll
            for (int b = 0; b < 16; b++)
                cnt[b] += __shfl_down_sync(0xFFFFFFFFu, cnt[b], off);
        }
        if (lane == 0) {
            #pragma unroll
            for (int b = 0; b < 16; b++) atomicAdd(&s_tot[b], cnt[b]);
        }
        __syncthreads();
        // every thread picks the crossing bucket (deterministic)
        int cum = above, bstar = 0;
        #pragma unroll
        for (int b = 15; b >= 0; b--) {
            int tb = s_tot[b];
            if (cum + tb >= KC) { bstar = b; break; }
            cum += tb;
        }
        above = cum;
        active = s_tot[bstar];
        pref |= (unsigned)bstar << sh;
        maskhi |= 0xFu << sh;
        pbits += 4;
        __syncthreads();   // protect s_tot before next-level rezero
        if (above + active <= STOP_CLASS || pbits >= 28) break;
    }

    // ---- gather all keys >= pref (count = above+active <= GCAP in practice) ----
    for (int i = t; i < GCAP; i += 512) U.keys[i] = 0ULL;
    if (t == 0) s_cnt = 0;
    __syncthreads();
    for (int a = t; a < N4; a += 512) {
        float4 v = row4[a];
        float vv[4] = {v.x, v.y, v.z, v.w};
        #pragma unroll
        for (int q = 0; q < 4; q++) {
            unsigned key = fkey(__float_as_uint(vv[q]));
            if (key >= pref) {
                int p = atomicAdd(&s_cnt, 1);
                if (p < GCAP) {
                    unsigned aidx = (unsigned)(a * 4 + q);
                    U.keys[p] = ((unsigned long long)key << 32) | (0xFFFFFFFFu - aidx);
                }
            }
        }
    }
    __syncthreads();

    // ---- bitonic sort descending of next_pow2(cnt) ----
    int cnt2 = s_cnt; if (cnt2 > GCAP) cnt2 = GCAP;
    int N = 512; while (N < cnt2) N <<= 1;
    for (int k2 = 2; k2 <= N; k2 <<= 1) {
        for (int j = k2 >> 1; j > 0; j >>= 1) {
            for (int i = t; i < N; i += 512) {
                int ix = i ^ j;
                if (ix > i) {
                    unsigned long long x = U.keys[i], y = U.keys[ix];
                    bool desc = ((i & k2) == 0);
                    if (desc ? (x < y) : (x > y)) { U.keys[i] = y; U.keys[ix] = x; }
                }
            }
            __syncthreads();
        }
    }

    // ---- extract top-512 (cnt >= 512 guaranteed): sigmoid + boxes ----
    {
        unsigned long long key = U.keys[t];
        unsigned kb  = (unsigned)(key >> 32);
        unsigned idx = 0xFFFFFFFFu - (unsigned)(key & 0xFFFFFFFFu);
        float x = __uint_as_float(fkey_inv(kb));
        float v = 1.0f / (1.0f + expf(-x));
        float4 b = g_boxes[idx];
        sval[t] = v;
        sbox[t] = b;
        sarea[t] = (b.z - b.x) * (b.w - b.y);
    }
    int nvalid = __syncthreads_count(sval[t] > THRESH);   // valid is a sorted prefix
    __syncthreads();   // sval/sbox/sarea visible; U.keys no longer needed

    // ---- build IoU>0.5 bit matrix (upper triangle), reusing U as bits ----
    if (t < nvalid) {
        float4 bt = sbox[t];
        float at = sarea[t];
        #pragma unroll 1
        for (int w = 0; w < 16; w++) {
            unsigned word = 0;
            int j0 = w * 32;
            int js = (t + 1 > j0) ? (t + 1) : j0;
            int je = j0 + 32;
            for (int j = js; j < je; j++) {
                float4 bj = sbox[j];
                float xx1 = fmaxf(bt.x, bj.x), yy1 = fmaxf(bt.y, bj.y);
                float xx2 = fminf(bt.z, bj.z), yy2 = fminf(bt.w, bj.w);
                float inter = fmaxf(xx2 - xx1, 0.0f) * fmaxf(yy2 - yy1, 0.0f);
                float iou = inter / (at + sarea[j] - inter + 1e-8f);
                word |= (unsigned)(iou > IOU_T) << (j - j0);
            }
            U.bits[t][w] = word;
        }
    }
    __syncthreads();

    // ---- serial greedy NMS scan by warp 0 (no block barriers) ----
    if (t < 32) {
        int l = t;
        unsigned valid_l = 0;
        if (l < 16) {
            int v = nvalid - l * 32;
            valid_l = (v >= 32) ? 0xFFFFFFFFu : ((v <= 0) ? 0u : ((1u << v) - 1u));
        }
        unsigned done = ~valid_l;      // invalid entries pre-marked done
        unsigned keepw = 0;
        while (true) {
            unsigned cand = ~done;
            unsigned ball = __ballot_sync(0xFFFFFFFFu, cand != 0u);
            if (!ball) break;
            int src = __ffs(ball) - 1;
            unsigned cw = __shfl_sync(0xFFFFFFFFu, cand, src);
            int i = src * 32 + __ffs(cw) - 1;
            if (l == src) { keepw |= 1u << (i & 31); done |= 1u << (i & 31); }
            unsigned rowb = (l < 16) ? U.bits[i][l] : 0u;
            done |= rowb;
        }
        if (l < 16) s_keep[l] = keepw;
    }
    __syncthreads();

    bool keep = (s_keep[t >> 5] >> (t & 31)) & 1u;
    g_kept[c * KC + t]   = keep ? sval[t] : -1.0f;
    g_cboxes[c * KC + t] = sbox[t];
}

// ---------------- K4: final top-100 via radix select + output ----------------
__global__ void __launch_bounds__(1024) k_final(float* __restrict__ out) {
    __shared__ unsigned long long keys[FCAP];   // 16 KB
    __shared__ int s_tot[16];
    __shared__ int s_cnt;
    const int t = threadIdx.x;
    const int lane = t & 31;
    const float4* kept4 = (const float4*)g_kept;
    const int N4 = TOT / 4;

    unsigned pref = 0, maskhi = 0;
    int pbits = 0, above = 0, active = 0;

    while (true) {
        if (t < 16) s_tot[t] = 0;
        __syncthreads();
        const int sh = 28 - pbits;
        unsigned long long accLo = 0, accHi = 0;
        for (int a = t; a < N4; a += 1024) {
            float4 v = kept4[a];
            float vv[4] = {v.x, v.y, v.z, v.w};
            #pragma unroll
            for (int q = 0; q < 4; q++) {
                unsigned u = __float_as_uint(vv[q]);
                unsigned m = (vv[q] > 0.0f && (u & maskhi) == pref) ? 1u : 0u;
                unsigned b = (u >> sh) & 15u;
                unsigned long long inc = (unsigned long long)m << ((b & 7u) * 8u);
                if (b < 8u) accLo += inc; else accHi += inc;
            }
        }
        int cnt[16];
        #pragma unroll
        for (int b = 0; b < 8; b++)  cnt[b]     = (int)((accLo >> (8 * b)) & 0xFF);
        #pragma unroll
        for (int b = 0; b < 8; b++)  cnt[b + 8] = (int)((accHi >> (8 * b)) & 0xFF);
        #pragma unroll
        for (int off = 16; off > 0; off >>= 1) {
            #pragma unroll
            for (int b = 0; b < 16; b++)
                cnt[b] += __shfl_down_sync(0xFFFFFFFFu, cnt[b], off);
        }
        if (lane == 0) {
            #pragma unroll
            for (int b = 0; b < 16; b++) atomicAdd(&s_tot[b], cnt[b]);
        }
        __syncthreads();
        int cum = above, bstar = 0;
        #pragma unroll
        for (int b = 15; b >= 0; b--) {
            int tb = s_tot[b];
            if (cum + tb >= MAXDET) { bstar = b; break; }
            cum += tb;
        }
        above = cum;
        active = s_tot[bstar];
        pref |= (unsigned)bstar << sh;
        maskhi |= 0xFu << sh;
        pbits += 4;
        __syncthreads();
        if (above + active <= STOP_FIN || pbits >= 28) break;
    }

    for (int i = t; i < FCAP; i += 1024) keys[i] = 0ULL;
    if (t == 0) s_cnt = 0;
    __syncthreads();
    for (int a = t; a < N4; a += 1024) {
        float4 v = kept4[a];
        float vv[4] = {v.x, v.y, v.z, v.w};
        #pragma unroll
        for (int q = 0; q < 4; q++) {
            unsigned u = __float_as_uint(vv[q]);
            if (vv[q] > 0.0f && u >= pref) {
                int p = atomicAdd(&s_cnt, 1);
                if (p < FCAP) {
                    unsigned fi = (unsigned)(a * 4 + q);
                    keys[p] = ((unsigned long long)u << 32) | (0xFFFFFFFFu - fi);
                }
            }
        }
    }
    __syncthreads();

    int cnt2 = s_cnt; if (cnt2 > FCAP) cnt2 = FCAP;
    int N = 128; while (N < cnt2) N <<= 1;
    for (int k2 = 2; k2 <= N; k2 <<= 1) {
        for (int j = k2 >> 1; j > 0; j >>= 1) {
            for (int i = t; i < N; i += 1024) {
                int ix = i ^ j;
                if (ix > i) {
                    unsigned long long x = keys[i], y = keys[ix];
                    bool d = ((i & k2) == 0);
                    if (d ? (x < y) : (x > y)) { keys[i] = y; keys[ix] = x; }
                }
            }
            __syncthreads();
        }
    }

    if (t < MAXDET) {
        unsigned long long key = keys[t];
        float* rowp = out + t * 7;
        if (key == 0ULL) {
            #pragma unroll
            for (int q = 0; q < 7; q++) rowp[q] = 0.0f;
        } else {
            unsigned ub = (unsigned)(key >> 32);
            unsigned flat = 0xFFFFFFFFu - (unsigned)(key & 0xFFFFFFFFu);
            float v = __uint_as_float(ub);
            float4 bb = g_cboxes[flat];
            rowp[0] = 0.0f;
            rowp[1] = bb.x; rowp[2] = bb.y; rowp[3] = bb.z; rowp[4] = bb.w;
            rowp[5] = v;
            rowp[6] = (float)(flat / KC);
        }
    }
}

// ---------------- launch ----------------
extern "C" void kernel_launch(void* const* d_in, const int* in_sizes, int n_in,
                              void* d_out, int out_size) {
    const float* reg = (const float*)d_in[1];
    const float* cls = (const float*)d_in[2];
    const float* anc = (const float*)d_in[3];
    float* out = (float*)d_out;

    k_decode<<<(A_N + 255) / 256, 256>>>(reg, anc);
    k_transpose<<<dim3((A_N + 31) / 32, (C_N + 31) / 32), dim3(32, 32)>>>(cls);
    k_class<<<C_N, 512>>>();
    k_final<<<1, 1024>>>(out);
}

// round 6
// speedup vs baseline: 1.6691x; 1.2298x over previous
#include <cuda_runtime.h>
#include <cuda_bf16.h>
#include <math.h>
#include <stdint.h>

#define A_N 110484          // anchors
#define C_N 90              // classes
#define KC  512             // K_CAND
#define IMGF 768.0f
#define THRESH 0.05f
#define IOU_T 0.5f
#define MAXDET 100
#define GCAP 4096           // gather capacity (u64 keys) in k_class
#define TOPC 128            // per-class compacted kept slots (>=100 is lossless)
#define POOL (C_N * TOPC)   // 11520
#define FSEL 1024           // k_final compaction capacity

// ---------------- scratch (device globals) ----------------
__device__ float  g_xT[(size_t)C_N * A_N];            // (90, A) raw logits transposed
__device__ float4 g_cboxes[C_N * KC];                 // per-class candidate boxes (sorted slot order)
__device__ unsigned long long g_top[POOL];            // per-class kept keys (score_bits<<32 | ~flat)

// order-preserving transform: float total order -> unsigned order
__device__ __forceinline__ unsigned fkey(unsigned u) {
    return u ^ ((u & 0x80000000u) ? 0xFFFFFFFFu : 0x80000000u);
}
__device__ __forceinline__ unsigned fkey_inv(unsigned k) {
    return (k & 0x80000000u) ? (k ^ 0x80000000u) : ~k;
}

// ---------------- K1: transpose (raw logits), float4 stores ----------------
__global__ void __launch_bounds__(256) k_transpose(const float* __restrict__ cls) {
    __shared__ float tile[32][33];
    const int ta = blockIdx.x * 32;       // anchor base
    const int tc = blockIdx.y * 32;       // class base
    const int tx = threadIdx.x, ty = threadIdx.y;   // (32, 8)
    #pragma unroll
    for (int k = 0; k < 4; k++) {
        int a = ta + ty + k * 8;
        int c = tc + tx;
        if (a < A_N && c < C_N)
            tile[ty + k * 8][tx] = cls[(size_t)a * C_N + c];
    }
    __syncthreads();
    int tid = ty * 32 + tx;               // 0..255
    int c_l = tid >> 3;                   // 0..31
    int a4  = (tid & 7) * 4;              // 0,4,...,28
    int c2 = tc + c_l;
    int a0 = ta + a4;
    if (c2 < C_N) {
        if (a0 + 3 < A_N) {
            float4 v = make_float4(tile[a4][c_l], tile[a4 + 1][c_l],
                                   tile[a4 + 2][c_l], tile[a4 + 3][c_l]);
            *(float4*)&g_xT[(size_t)c2 * A_N + a0] = v;
        } else {
            for (int q = 0; q < 4 && a0 + q < A_N; q++)
                g_xT[(size_t)c2 * A_N + a0 + q] = tile[a4 + q][c_l];
        }
    }
}

// ---------------- K2: fused per-class select + sort + decode + NMS --------
__global__ void __launch_bounds__(512) k_class(const float* __restrict__ reg,
                                               const float* __restrict__ anc) {
    __shared__ union {
        unsigned long long keys[GCAP];     // 32 KB gather buffer
        unsigned bits[KC][16];             // 32 KB IoU suppression matrix
    } U;
    __shared__ union {
        float4 box[KC];                    // 8 KB survivor boxes
        unsigned long long B[2 * KC];      // 8 KB compact/sort buffer
    } V;
    __shared__ float  sval[KC];            // 2 KB
    __shared__ float  sarea[KC];           // 2 KB
    __shared__ int    s_tot[16];
    __shared__ int    s_cnt;
    __shared__ unsigned s_keep[16];

    const int c = blockIdx.x, t = threadIdx.x;
    const int lane = t & 31;
    const float4* row4 = (const float4*)&g_xT[(size_t)c * A_N];
    const int N4 = A_N / 4;

    // zero this class's g_top slice (scatter happens after barriers below)
    if (t < TOPC) g_top[c * TOPC + t] = 0ULL;

    unsigned pref = 0, maskhi = 0;
    int pbits = 0, above = 0;
    int ncand = A_N;

    // ---- global radix narrowing until candidate count <= GCAP ----
    while (true) {
        if (t < 16) s_tot[t] = 0;
        __syncthreads();
        const int sh = 28 - pbits;
        unsigned long long accLo = 0, accHi = 0;
        #pragma unroll 4
        for (int a = t; a < N4; a += 512) {
            float4 v = row4[a];
            float vv[4] = {v.x, v.y, v.z, v.w};
            #pragma unroll
            for (int q = 0; q < 4; q++) {
                unsigned key = fkey(__float_as_uint(vv[q]));
                unsigned m = ((key & maskhi) == pref) ? 1u : 0u;
                unsigned b = (key >> sh) & 15u;
                unsigned long long inc = (unsigned long long)m << ((b & 7u) * 8u);
                if (b < 8u) accLo += inc; else accHi += inc;
            }
        }
        int cnt[16];
        #pragma unroll
        for (int b = 0; b < 8; b++)  cnt[b]     = (int)((accLo >> (8 * b)) & 0xFF);
        #pragma unroll
        for (int b = 0; b < 8; b++)  cnt[b + 8] = (int)((accHi >> (8 * b)) & 0xFF);
        #pragma unroll
        for (int off = 16; off > 0; off >>= 1) {
            #pragma unroll
            for (int b = 0; b < 16; b++)
                cnt[b] += __shfl_down_sync(0xFFFFFFFFu, cnt[b], off);
        }
        if (lane == 0) {
            #pragma unroll
            for (int b = 0; b < 16; b++) atomicAdd(&s_tot[b], cnt[b]);
        }
        __syncthreads();
        int mtot = 0;
        #pragma unroll
        for (int b = 0; b < 16; b++) mtot += s_tot[b];
        if (above + mtot <= GCAP) { ncand = above + mtot; __syncthreads(); break; }
        int cum = above, bstar = 0;
        #pragma unroll
        for (int b = 15; b >= 0; b--) {
            int tb = s_tot[b];
            if (cum + tb >= KC) { bstar = b; break; }
            cum += tb;
        }
        above = cum;
        int active = s_tot[bstar];
        pref |= (unsigned)bstar << sh;
        maskhi |= 0xFu << sh;
        pbits += 4;
        ncand = above + active;
        __syncthreads();               // protect s_tot before next rezero
        if (ncand <= GCAP || pbits >= 28) break;
    }

    // ---- gather all keys >= pref into shared ----
    for (int i = t; i < GCAP; i += 512) U.keys[i] = 0ULL;
    if (t == 0) s_cnt = 0;
    __syncthreads();
    #pragma unroll 4
    for (int a = t; a < N4; a += 512) {
        float4 v = row4[a];
        float vv[4] = {v.x, v.y, v.z, v.w};
        #pragma unroll
        for (int q = 0; q < 4; q++) {
            unsigned key = fkey(__float_as_uint(vv[q]));
            if (key >= pref) {
                int p = atomicAdd(&s_cnt, 1);
                if (p < GCAP) {
                    unsigned aidx = (unsigned)(a * 4 + q);
                    U.keys[p] = ((unsigned long long)key << 32) | ~aidx;
                }
            }
        }
    }
    __syncthreads();
    int cnt2 = s_cnt; if (cnt2 > GCAP) cnt2 = GCAP;

    // ---- shared radix refinement until candidate count <= 1024 ----
    while (ncand > 2 * KC && pbits < 32) {
        if (t < 16) s_tot[t] = 0;
        __syncthreads();
        const int sh = 28 - pbits;
        unsigned long long accLo = 0, accHi = 0;
        for (int i = t; i < cnt2; i += 512) {
            unsigned key = (unsigned)(U.keys[i] >> 32);
            unsigned m = ((key & maskhi) == pref) ? 1u : 0u;
            unsigned b = (key >> sh) & 15u;
            unsigned long long inc = (unsigned long long)m << ((b & 7u) * 8u);
            if (b < 8u) accLo += inc; else accHi += inc;
        }
        int cnt[16];
        #pragma unroll
        for (int b = 0; b < 8; b++)  cnt[b]     = (int)((accLo >> (8 * b)) & 0xFF);
        #pragma unroll
        for (int b = 0; b < 8; b++)  cnt[b + 8] = (int)((accHi >> (8 * b)) & 0xFF);
        #pragma unroll
        for (int off = 16; off > 0; off >>= 1) {
            #pragma unroll
            for (int b = 0; b < 16; b++)
                cnt[b] += __shfl_down_sync(0xFFFFFFFFu, cnt[b], off);
        }
        if (lane == 0) {
            #pragma unroll
            for (int b = 0; b < 16; b++) atomicAdd(&s_tot[b], cnt[b]);
        }
        __syncthreads();
        int mtot = 0;
        #pragma unroll
        for (int b = 0; b < 16; b++) mtot += s_tot[b];
        if (above + mtot <= 2 * KC) { ncand = above + mtot; __syncthreads(); break; }
        int cum = above, bstar = 0;
        #pragma unroll
        for (int b = 15; b >= 0; b--) {
            int tb = s_tot[b];
            if (cum + tb >= KC) { bstar = b; break; }
            cum += tb;
        }
        above = cum;
        int active = s_tot[bstar];
        pref |= (unsigned)bstar << sh;
        maskhi |= 0xFu << sh;
        pbits += 4;
        ncand = above + active;
        __syncthreads();
    }

    // ---- compact keys >= pref into V.B, zero-padded, then sort desc ----
    V.B[t] = 0ULL; V.B[t + 512] = 0ULL;
    if (t == 0) s_cnt = 0;
    __syncthreads();
    for (int i = t; i < cnt2; i += 512) {
        unsigned long long kk = U.keys[i];
        if ((unsigned)(kk >> 32) >= pref) {
            int p = atomicAdd(&s_cnt, 1);
            if (p < 2 * KC) V.B[p] = kk;
        }
    }
    __syncthreads();
    int cnt3 = s_cnt; if (cnt3 > 2 * KC) cnt3 = 2 * KC;
    int N = 512; while (N < cnt3) N <<= 1;      // 512 or 1024
    for (int k2 = 2; k2 <= N; k2 <<= 1) {
        for (int j = k2 >> 1; j > 0; j >>= 1) {
            for (int i = t; i < N; i += 512) {
                int ix = i ^ j;
                if (ix > i) {
                    unsigned long long x = V.B[i], y = V.B[ix];
                    bool desc = ((i & k2) == 0);
                    if (desc ? (x < y) : (x > y)) { V.B[i] = y; V.B[ix] = x; }
                }
            }
            __syncthreads();
        }
    }

    // ---- extract top-512: sigmoid + on-demand box decode ----
    unsigned long long mykey = V.B[t];
    __syncthreads();                  // all reads of V.B done before V.box overwrite
    float4 b4;
    float v, area;
    {
        unsigned kb  = (unsigned)(mykey >> 32);
        unsigned idx = ~(unsigned)(mykey & 0xFFFFFFFFu);
        float x = __uint_as_float(fkey_inv(kb));
        v = 1.0f / (1.0f + expf(-x));
        float4 a = ((const float4*)anc)[idx];
        float4 d = ((const float4*)reg)[idx];
        float wa = a.z - a.x, ha = a.w - a.y;
        float cxa = a.x + 0.5f * wa, cya = a.y + 0.5f * ha;
        float cx = cxa + d.x * wa;
        float cy = cya + d.y * ha;
        float w = expf(d.z) * wa;
        float h = expf(d.w) * ha;
        b4.x = fminf(fmaxf(cx - 0.5f * w, 0.0f), IMGF);
        b4.y = fminf(fmaxf(cy - 0.5f * h, 0.0f), IMGF);
        b4.z = fminf(fmaxf(cx + 0.5f * w, 0.0f), IMGF);
        b4.w = fminf(fmaxf(cy + 0.5f * h, 0.0f), IMGF);
        area = (b4.z - b4.x) * (b4.w - b4.y);
        sval[t] = v;
        V.box[t] = b4;
        sarea[t] = area;
    }
    int nvalid = __syncthreads_count(v > THRESH);   // valid is a sorted prefix

    // ---- build IoU > 0.5 bit matrix (upper triangle) in U.bits ----
    if (t < nvalid) {
        #pragma unroll 1
        for (int w = 0; w < 16; w++) {
            unsigned word = 0;
            int j0 = w * 32;
            int js = (t + 1 > j0) ? (t + 1) : j0;
            int je = j0 + 32;
            for (int j = js; j < je; j++) {
                float4 bj = V.box[j];
                float xx1 = fmaxf(b4.x, bj.x), yy1 = fmaxf(b4.y, bj.y);
                float xx2 = fminf(b4.z, bj.z), yy2 = fminf(b4.w, bj.w);
                float inter = fmaxf(xx2 - xx1, 0.0f) * fmaxf(yy2 - yy1, 0.0f);
                float iou = inter / (area + sarea[j] - inter + 1e-8f);
                word |= (unsigned)(iou > IOU_T) << (j - j0);
            }
            U.bits[t][w] = word;
        }
    }
    __syncthreads();

    // ---- serial greedy NMS scan by warp 0 ----
    if (t < 32) {
        int l = t;
        unsigned valid_l = 0;
        if (l < 16) {
            int vv = nvalid - l * 32;
            valid_l = (vv >= 32) ? 0xFFFFFFFFu : ((vv <= 0) ? 0u : ((1u << vv) - 1u));
        }
        unsigned done = ~valid_l;
        unsigned keepw = 0;
        while (true) {
            unsigned cand = ~done;
            unsigned ball = __ballot_sync(0xFFFFFFFFu, cand != 0u);
            if (!ball) break;
            int src = __ffs(ball) - 1;
            unsigned cw = __shfl_sync(0xFFFFFFFFu, cand, src);
            int i = src * 32 + __ffs(cw) - 1;
            if (l == src) { keepw |= 1u << (i & 31); done |= 1u << (i & 31); }
            unsigned rowb = (l < 16) ? U.bits[i][l] : 0u;
            done |= rowb;
        }
        if (l < 16) s_keep[l] = keepw;
    }
    __syncthreads();

    // ---- outputs: boxes for all 512 slots, compacted kept keys ----
    g_cboxes[c * KC + t] = b4;
    int w = t >> 5, bb = t & 31;
    bool keep = (s_keep[w] >> bb) & 1u;
    int rank = __popc(s_keep[w] & ((bb == 0) ? 0u : ((1u << bb) - 1u)));
    for (int i = 0; i < w; i++) rank += __popc(s_keep[i]);
    if (keep && rank < TOPC) {
        unsigned flat = (unsigned)(c * KC + t);
        g_top[c * TOPC + rank] =
            ((unsigned long long)__float_as_uint(sval[t]) << 32) | ~flat;
    }
}

// ---------------- K3: final top-100 over compacted pool + output ----------------
__global__ void __launch_bounds__(1024) k_final(float* __restrict__ out) {
    __shared__ unsigned long long B[FSEL];   // 8 KB
    __shared__ int s_tot[16];
    __shared__ int s_cnt;
    const int t = threadIdx.x;
    const int lane = t & 31;

    // all sigmoid scores in (0.05, 1) share top nibble 0x3 -> start at pbits=4
    unsigned pref = 0x30000000u, maskhi = 0xF0000000u;
    int pbits = 4, above = 0;
    int ncand = POOL;

    while (pbits < 32) {
        if (t < 16) s_tot[t] = 0;
        __syncthreads();
        const int sh = 28 - pbits;
        unsigned long long accLo = 0, accHi = 0;
        #pragma unroll 4
        for (int i = t; i < POOL; i += 1024) {
            unsigned key = (unsigned)(g_top[i] >> 32);
            unsigned m = ((key & maskhi) == pref) ? 1u : 0u;   // key==0 fails the match
            unsigned b = (key >> sh) & 15u;
            unsigned long long inc = (unsigned long long)m << ((b & 7u) * 8u);
            if (b < 8u) accLo += inc; else accHi += inc;
        }
        int cnt[16];
        #pragma unroll
        for (int b = 0; b < 8; b++)  cnt[b]     = (int)((accLo >> (8 * b)) & 0xFF);
        #pragma unroll
        for (int b = 0; b < 8; b++)  cnt[b + 8] = (int)((accHi >> (8 * b)) & 0xFF);
        #pragma unroll
        for (int off = 16; off > 0; off >>= 1) {
            #pragma unroll
            for (int b = 0; b < 16; b++)
                cnt[b] += __shfl_down_sync(0xFFFFFFFFu, cnt[b], off);
        }
        if (lane == 0) {
            #pragma unroll
            for (int b = 0; b < 16; b++) atomicAdd(&s_tot[b], cnt[b]);
        }
        __syncthreads();
        int mtot = 0;
        #pragma unroll
        for (int b = 0; b < 16; b++) mtot += s_tot[b];
        if (above + mtot <= FSEL) { ncand = above + mtot; __syncthreads(); break; }
        int cum = above, bstar = 0;
        #pragma unroll
        for (int b = 15; b >= 0; b--) {
            int tb = s_tot[b];
            if (cum + tb >= MAXDET) { bstar = b; break; }
            cum += tb;
        }
        above = cum;
        int active = s_tot[bstar];
        pref |= (unsigned)bstar << sh;
        maskhi |= 0xFu << sh;
        pbits += 4;
        ncand = above + active;
        __syncthreads();
        if (ncand <= FSEL) break;
    }

    // compact keys >= pref into shared (zero-padded)
    if (t < FSEL) B[t] = 0ULL;
    if (t == 0) s_cnt = 0;
    __syncthreads();
    for (int i = t; i < POOL; i += 1024) {
        unsigned long long kk = g_top[i];
        if ((unsigned)(kk >> 32) >= pref) {
            int p = atomicAdd(&s_cnt, 1);
            if (p < FSEL) B[p] = kk;
        }
    }
    __syncthreads();
    int cnt2 = s_cnt; if (cnt2 > FSEL) cnt2 = FSEL;
    int N = 128; while (N < cnt2) N <<= 1;
    for (int k2 = 2; k2 <= N; k2 <<= 1) {
        for (int j = k2 >> 1; j > 0; j >>= 1) {
            for (int i = t; i < N; i += 1024) {
                int ix = i ^ j;
                if (ix > i) {
                    unsigned long long x = B[i], y = B[ix];
                    bool d = ((i & k2) == 0);
                    if (d ? (x < y) : (x > y)) { B[i] = y; B[ix] = x; }
                }
            }
            __syncthreads();
        }
    }

    if (t < MAXDET) {
        unsigned long long key = B[t];
        float* rowp = out + t * 7;
        if (key == 0ULL) {
            #pragma unroll
            for (int q = 0; q < 7; q++) rowp[q] = 0.0f;
        } else {
            unsigned ub   = (unsigned)(key >> 32);
            unsigned flat = ~(unsigned)(key & 0xFFFFFFFFu);
            float v = __uint_as_float(ub);
            float4 bb = g_cboxes[flat];
            rowp[0] = 0.0f;
            rowp[1] = bb.x; rowp[2] = bb.y; rowp[3] = bb.z; rowp[4] = bb.w;
            rowp[5] = v;
            rowp[6] = (float)(flat / KC);
        }
    }
}

// ---------------- launch ----------------
extern "C" void kernel_launch(void* const* d_in, const int* in_sizes, int n_in,
                              void* d_out, int out_size) {
    const float* reg = (const float*)d_in[1];
    const float* cls = (const float*)d_in[2];
    const float* anc = (const float*)d_in[3];
    float* out = (float*)d_out;

    k_transpose<<<dim3((A_N + 31) / 32, (C_N + 31) / 32), dim3(32, 8)>>>(cls);
    k_class<<<C_N, 512>>>(reg, anc);
    k_final<<<1, 1024>>>(out);
}